// round 15
// baseline (speedup 1.0000x reference)
#include <cuda_runtime.h>
#include <cuda_fp16.h>
#include <cstdint>

// Shapes: x[4096,4096] fp32, codes[4096,4096] int32(0..15),
//         absmax[4096,64] fp32, bias[4096] fp32, out[4096,4096] fp32
#define M_DIM 4096
#define N_DIM 4096
#define K_DIM 4096

__device__ __half g_w[(size_t)N_DIM * K_DIM];   // [n][k] fp16
__device__ __half g_x[(size_t)M_DIM * K_DIM];   // [m][k] fp16

__constant__ float c_nf4[16] = {
    -1.0f, -0.6961928009986877f, -0.5250730514526367f, -0.39491748809814453f,
    -0.28444138169288635f, -0.18477343022823334f, -0.09105003625154495f, 0.0f,
    0.07958029955625534f, 0.16093020141124725f, 0.24611230194568634f,
    0.33791524171829224f, 0.44070982933044434f, 0.5626170039176941f,
    0.6797559261322021f, 1.0f};

// ---------------------------------------------------------------------------
// Fused prep: NF4 dequant -> g_w (fp16), x fp32 -> g_x (fp16). 8 elems/thread.
// ---------------------------------------------------------------------------
#define PW ((N_DIM * K_DIM / 8) / 256)   // 8192
#define PX ((M_DIM * K_DIM / 8) / 256)   // 8192

__global__ void __launch_bounds__(256) prep_kernel(
    const int* __restrict__ codes, const float* __restrict__ absmax,
    const float* __restrict__ x) {
    if (blockIdx.x < PW) {
        int i = blockIdx.x * 256 + threadIdx.x;     // 8-elem index
        int k8 = i & 511;                           // K/8 = 512
        int n  = i >> 9;
        const int4* cp = (const int4*)codes + (size_t)i * 2;
        int4 c0 = __ldg(cp), c1 = __ldg(cp + 1);
        float s = __ldg(absmax + n * 64 + (k8 >> 3));
        __half2 h[4];
        h[0] = __floats2half2_rn(c_nf4[c0.x] * s, c_nf4[c0.y] * s);
        h[1] = __floats2half2_rn(c_nf4[c0.z] * s, c_nf4[c0.w] * s);
        h[2] = __floats2half2_rn(c_nf4[c1.x] * s, c_nf4[c1.y] * s);
        h[3] = __floats2half2_rn(c_nf4[c1.z] * s, c_nf4[c1.w] * s);
        *(uint4*)(g_w + (size_t)i * 8) = *(uint4*)h;
    } else {
        int i = (blockIdx.x - PW) * 256 + threadIdx.x;
        const float4* xp = (const float4*)x + (size_t)i * 2;
        float4 v0 = __ldg(xp), v1 = __ldg(xp + 1);
        __half2 h[4];
        h[0] = __floats2half2_rn(v0.x, v0.y);
        h[1] = __floats2half2_rn(v0.z, v0.w);
        h[2] = __floats2half2_rn(v1.x, v1.y);
        h[3] = __floats2half2_rn(v1.z, v1.w);
        *(uint4*)(g_x + (size_t)i * 8) = *(uint4*)h;
    }
}

// ---------------------------------------------------------------------------
// GEMM: fp16 mma.sync.m16n8k16, fp32 accumulate.
// CTA tile 256x128x32, 8 warps, warp tile 64x64, 4-stage cp.async ring,
// one __syncthreads per k-iteration. Fragment algebra identical to the
// hardware-verified round-5 kernel.
// ---------------------------------------------------------------------------
#define BM 256
#define BN 128
#define BK 32
#define PAD 8                      // row stride 40 halves -> conflict-free ldmatrix
#define RS (BK + PAD)              // 40
#define STAGES 4
#define A_H (BM * RS)              // 10240 halves = 20 KB
#define B_H (BN * RS)              // 5120 halves = 10 KB
#define SMEM_BYTES (STAGES * (A_H + B_H) * 2)   // 122880

__device__ __forceinline__ void mma16816(float c[4], const uint32_t a[4],
                                         const uint32_t b[2]) {
    asm volatile(
        "mma.sync.aligned.m16n8k16.row.col.f32.f16.f16.f32 "
        "{%0,%1,%2,%3}, {%4,%5,%6,%7}, {%8,%9}, {%0,%1,%2,%3};\n"
        : "+f"(c[0]), "+f"(c[1]), "+f"(c[2]), "+f"(c[3])
        : "r"(a[0]), "r"(a[1]), "r"(a[2]), "r"(a[3]), "r"(b[0]), "r"(b[1]));
}
__device__ __forceinline__ void ldsm_x4(uint32_t r[4], uint32_t saddr) {
    asm volatile(
        "ldmatrix.sync.aligned.m8n8.x4.shared.b16 {%0,%1,%2,%3}, [%4];\n"
        : "=r"(r[0]), "=r"(r[1]), "=r"(r[2]), "=r"(r[3]) : "r"(saddr));
}
__device__ __forceinline__ void cp_async16(uint32_t sa, const void* g) {
    asm volatile("cp.async.ca.shared.global [%0], [%1], 16;\n" :: "r"(sa), "l"(g));
}
__device__ __forceinline__ void cp_commit() {
    asm volatile("cp.async.commit_group;\n" ::: "memory");
}
template <int N>
__device__ __forceinline__ void cp_wait() {
    asm volatile("cp.async.wait_group %0;\n" :: "n"(N) : "memory");
}

__global__ void __launch_bounds__(256, 1) gemm_kernel(
    const float* __restrict__ bias, float* __restrict__ out) {
    extern __shared__ __half smem[];
    __half* As = smem;                 // STAGES x [BM][RS]
    __half* Bs = smem + STAGES * A_H;  // STAGES x [BN][RS]

    const int tid  = threadIdx.x;
    const int warp = tid >> 5;
    const int lane = tid & 31;
    const int g    = lane >> 2;   // 0..7
    const int tg   = lane & 3;    // 0..3

    const int wm = (warp & 3) * 64;     // warp M offset (0..192)
    const int wn = (warp >> 2) * 64;    // warp N offset (0 or 64)

    const int bm = blockIdx.y * BM;
    const int bn = blockIdx.x * BN;

    const __half* A = g_x;
    const __half* B = g_w;

    // gmem->smem: A 1024 vec16 (4/thread), B 512 vec16 (2/thread)
    const int r0 = tid >> 2;              // 0..63
    const int c0 = (tid & 3) * 8;

    // ldmatrix lane address: row = lane&15, k-half = (lane>>4)*8
    const int lrow  = lane & 15;
    const int lcolh = (lane >> 4) * 8;

    float acc[4][8][4];
    #pragma unroll
    for (int mt = 0; mt < 4; mt++)
        #pragma unroll
        for (int nt = 0; nt < 8; nt++)
            #pragma unroll
            for (int e = 0; e < 4; e++) acc[mt][nt][e] = 0.0f;

    auto load_tile = [&](int n) {
        const int s = n % STAGES;
        __half* as = As + s * A_H;
        __half* bs = Bs + s * B_H;
        const int kt = n * BK;
        #pragma unroll
        for (int i = 0; i < 4; i++) {          // A: 256 rows
            int row = r0 + i * 64;
            cp_async16((uint32_t)__cvta_generic_to_shared(&as[row * RS + c0]),
                       &A[(size_t)(bm + row) * K_DIM + kt + c0]);
        }
        #pragma unroll
        for (int i = 0; i < 2; i++) {          // B: 128 rows
            int row = r0 + i * 64;
            cp_async16((uint32_t)__cvta_generic_to_shared(&bs[row * RS + c0]),
                       &B[(size_t)(bn + row) * K_DIM + kt + c0]);
        }
        cp_commit();
    };

    // prologue: prefetch tiles 0,1,2
    load_tile(0);
    load_tile(1);
    load_tile(2);

    const int NT = K_DIM / BK;           // 128
    for (int t = 0; t < NT; t++) {
        // ensure tile t resident (leave up to 2 younger groups in flight)
        if (t < NT - 2) cp_wait<2>();
        else if (t == NT - 2) cp_wait<1>();
        else cp_wait<0>();
        __syncthreads();
        // prefetch t+3 into stage (t+3)%4 = (t-1)%4; its readers (iter t-1)
        // all passed the barrier above -> single sync per iteration is safe
        if (t + 3 < NT) load_tile(t + 3);

        const __half* as = As + (t % STAGES) * A_H;
        const __half* bs = Bs + (t % STAGES) * B_H;

        #pragma unroll
        for (int ks = 0; ks < BK; ks += 16) {
            uint32_t a[4][4];
            uint32_t bf[4][4];   // 4 x4 groups cover 64 n-rows (two nt each)
            #pragma unroll
            for (int mt = 0; mt < 4; mt++) {
                uint32_t sa = (uint32_t)__cvta_generic_to_shared(
                    &as[(wm + mt * 16 + lrow) * RS + ks + lcolh]);
                ldsm_x4(a[mt], sa);
            }
            #pragma unroll
            for (int p = 0; p < 4; p++) {
                uint32_t sb = (uint32_t)__cvta_generic_to_shared(
                    &bs[(wn + p * 16 + lrow) * RS + ks + lcolh]);
                ldsm_x4(bf[p], sb);
            }
            #pragma unroll
            for (int mt = 0; mt < 4; mt++) {
                #pragma unroll
                for (int nt = 0; nt < 8; nt++) {
                    int p = nt >> 1, h = nt & 1;
                    uint32_t b2[2] = {bf[p][h], bf[p][h + 2]};
                    mma16816(acc[mt][nt], a[mt], b2);
                }
            }
        }
    }

    // ---- epilogue: bias add + nonfinite clamp, STG.64 ----
    #pragma unroll
    for (int mt = 0; mt < 4; mt++) {
        #pragma unroll
        for (int nt = 0; nt < 8; nt++) {
            int r = bm + wm + mt * 16 + g;
            int c = bn + wn + nt * 8 + tg * 2;
            float b0 = __ldg(bias + c);
            float b1 = __ldg(bias + c + 1);
            float v0 = acc[mt][nt][0] + b0;
            float v1 = acc[mt][nt][1] + b1;
            float v2 = acc[mt][nt][2] + b0;
            float v3 = acc[mt][nt][3] + b1;
            if (!isfinite(v0)) v0 = 0.0f;
            if (!isfinite(v1)) v1 = 0.0f;
            if (!isfinite(v2)) v2 = 0.0f;
            if (!isfinite(v3)) v3 = 0.0f;
            *(float2*)&out[(size_t)r * N_DIM + c]       = make_float2(v0, v1);
            *(float2*)&out[(size_t)(r + 8) * N_DIM + c] = make_float2(v2, v3);
        }
    }
}

// ---------------------------------------------------------------------------
extern "C" void kernel_launch(void* const* d_in, const int* in_sizes, int n_in,
                              void* d_out, int out_size) {
    const float* x      = (const float*)d_in[0];
    const int*   codes  = (const int*)d_in[1];
    const float* absmax = (const float*)d_in[2];
    const float* bias   = (const float*)d_in[3];
    for (int i = 2; i < n_in && i < 4; i++) {
        if (in_sizes[i] == N_DIM * 64) absmax = (const float*)d_in[i];
        else if (in_sizes[i] == N_DIM) bias = (const float*)d_in[i];
    }
    float* out = (float*)d_out;

    prep_kernel<<<PW + PX, 256>>>(codes, absmax, x);

    cudaFuncSetAttribute(gemm_kernel,
                         cudaFuncAttributeMaxDynamicSharedMemorySize, SMEM_BYTES);
    dim3 grid(N_DIM / BN, M_DIM / BM);   // (32, 16)
    gemm_kernel<<<grid, 256, SMEM_BYTES>>>(bias, out);
}